// round 8
// baseline (speedup 1.0000x reference)
#include <cuda_runtime.h>
#include <math.h>

#define NCTA   128
#define NTHR   512
#define TSTEPS 1024
#define BATCH  64
#define HID    512
#define HB     (HID * BATCH)   // 32768
#define BT     (BATCH * TSTEPS)
#define BH     (BATCH * HID)

typedef unsigned long long u64;

// ---------------- global scratch (allocation-free) --------------------------
__device__ float    g_h0[2][HB];        // transposed: h[k*64 + b]
__device__ float    g_h1[2][HB];
__device__ float    g_yacc[2][BATCH];   // pre-relu y2 accumulators
__device__ unsigned g_flags[NCTA];      // per-CTA arrival generation
__device__ unsigned g_gen;              // broadcast generation

// ---------------- smem layout (float offsets) -------------------------------
// Weights k-major: w[k][gate]; gate-pairs feed f32x2 lanes.
// Arena overlap (timeline-safe):
//   redBi = arena + 0       (12288)  pass-X Bi partials
//   redA  = arena + 12288   (12288)  pass-X A(t+1) partials (reduced under beta)
//   redC  = arena + 12288   (4096)   pass-Y C partials      (after A reduced)
//   redBh = arena + 16384   (12288)  pass-Y Bh(t+1) partials (reduced under
//                                    next step's alpha, before pass-X writes)
#define OFF_WA    0          // Whh0: 512 x 12 = 6144
#define OFF_WBI   6144       // Wih1            = 6144
#define OFF_WBH   12288      // Whh1            = 6144
#define OFF_WC    18432      // Wo1: 512 x 4    = 2048
#define OFF_BASE  20480      // gi0 ctx part: 12x64 = 768
#define OFF_Y2    21248      // 256
#define OFF_MISC  21504      // wcolA12 bhhA12 biB12 bhB12 bC4 wo2_4 = 56 (pad 64)
#define OFF_ARENA 21568      // 28672
#define SMEM_FLOATS 50240
#define SMEM_BYTES  (SMEM_FLOATS * 4)   // 200,960 B

__device__ __forceinline__ void fma2(u64 &d, u64 a, u64 b) {
    asm("fma.rn.f32x2 %0, %1, %2, %0;" : "+l"(d) : "l"(a), "l"(b));
}
__device__ __forceinline__ u64 dup(float x) {
    u64 r; asm("mov.b64 %0, {%1, %1};" : "=l"(r) : "f"(x)); return r;
}
__device__ __forceinline__ float2 unpack2(u64 v) {
    float2 r; asm("mov.b64 {%0, %1}, %2;" : "=f"(r.x), "=f"(r.y) : "l"(v));
    return r;
}
__device__ __forceinline__ float sigm(float x) { return 1.0f / (1.0f + __expf(-x)); }
__device__ __forceinline__ float tanh_f(float x) {
    return 2.0f / (1.0f + __expf(-2.0f * x)) - 1.0f;
}
__device__ __forceinline__ unsigned ldacq(const unsigned* p) {
    unsigned v;
    asm volatile("ld.acquire.gpu.u32 %0, [%1];" : "=r"(v) : "l"(p) : "memory");
    return v;
}
__device__ __forceinline__ void strel(unsigned* p, unsigned v) {
    asm volatile("st.release.gpu.u32 [%0], %1;" :: "l"(p), "r"(v) : "memory");
}

// Split grid barrier; polling on threads 384..511 so waits overlap the
// 256-thread reduction work scheduled between arrive and wait.
__device__ __forceinline__ void bar_arrive(unsigned g) {
    __syncthreads();
    if (threadIdx.x == 0) strel(&g_flags[blockIdx.x], g);
}
__device__ __forceinline__ void bar_wait(unsigned g) {
    if (blockIdx.x == 0) {
        if (threadIdx.x >= 384) {
            while ((int)(ldacq(&g_flags[threadIdx.x - 384]) - g) < 0) { }
        }
        __syncthreads();
        if (threadIdx.x == 0) strel(&g_gen, g);
    } else {
        if (threadIdx.x == 384) {
            while ((int)(ldacq(&g_gen) - g) < 0) { }
        }
        __syncthreads();
    }
}

// Store 12 gate-pair accumulators (gates 2p,2p+1 x batches b0,b0+1).
__device__ __forceinline__ void store12(float* __restrict__ red, const u64* acc,
                                        int ks, int b0) {
    #pragma unroll
    for (int p = 0; p < 6; p++) {
        #pragma unroll
        for (int j = 0; j < 2; j++) {
            float2 f = unpack2(acc[2 * p + j]);
            red[((2 * p)     * 16 + ks) * 64 + b0 + j] = f.x;
            red[((2 * p + 1) * 16 + ks) * 64 + b0 + j] = f.y;
        }
    }
}

__global__ void __launch_bounds__(NTHR, 1)
decoder_rnn(const float* __restrict__ ctx,
            const float* __restrict__ Wih0, const float* __restrict__ Whh0,
            const float* __restrict__ bih0, const float* __restrict__ bhh0,
            const float* __restrict__ Wih1, const float* __restrict__ Whh1,
            const float* __restrict__ bih1, const float* __restrict__ bhh1,
            const float* __restrict__ Wo1,  const float* __restrict__ bo1,
            const float* __restrict__ Wo2,  const float* __restrict__ bo2p,
            float* __restrict__ out, int out_size)
{
    extern __shared__ float sm[];
    const int tid = threadIdx.x;
    const int cta = blockIdx.x;
    const int bp  = tid & 31;          // batch pair
    const int b0  = 2 * bp;
    const int ks  = tid >> 5;          // k-slice 0..15 (32 k each)
    const int kb  = ks * 32;
    const int be  = tid & 63;          // elementwise: batch (tid<256)
    const int re  = (tid >> 6) & 3;    // elementwise: local row 0..3
    const int jrow = cta * 4 + re;
    const int gR = re, gZ = 4 + re, gN = 8 + re;

    float* wA   = sm + OFF_WA;
    float* wBi  = sm + OFF_WBI;
    float* wBh  = sm + OFF_WBH;
    float* wC   = sm + OFF_WC;
    float* base = sm + OFF_BASE;
    float* y2   = sm + OFF_Y2;
    float* wcolA = sm + OFF_MISC;      // 12
    float* bhhA  = wcolA + 12;         // 12
    float* biB   = bhhA + 12;          // 12
    float* bhB   = biB + 12;           // 12
    float* bC    = bhB + 12;           // 4
    float* wo2s  = bC + 4;             // 4
    float* redBi = sm + OFF_ARENA;
    float* redA  = sm + OFF_ARENA + 12288;
    float* redC  = sm + OFF_ARENA + 12288;
    float* redBh = sm + OFF_ARENA + 16384;

    // ---- prelude: weights -> SMEM, k-major [k][gate] -----------------------
    for (int idx = tid; idx < 12 * 512; idx += NTHR) {
        int g = idx / 512, k = idx & 511;
        int grow = (g >> 2) * 512 + cta * 4 + (g & 3);
        wA [k * 12 + g] = Whh0[grow * 512 + k];
        wBi[k * 12 + g] = Wih1[grow * 512 + k];
        wBh[k * 12 + g] = Whh1[grow * 512 + k];
    }
    for (int idx = tid; idx < 4 * 512; idx += NTHR) {
        int r = idx / 512, k = idx & 511;
        wC[k * 4 + r] = Wo1[(cta * 4 + r) * 512 + k];
    }
    if (tid < 12) {
        int grow = (tid >> 2) * 512 + cta * 4 + (tid & 3);
        wcolA[tid] = Wih0[grow * 513 + 512];   // Wih0 is (1536, 513): prev col
        bhhA[tid]  = bhh0[grow];
        biB[tid]   = bih1[grow];
        bhB[tid]   = bhh1[grow];
    }
    if (tid < 4) {
        bC[tid]   = bo1[cta * 4 + tid];
        wo2s[tid] = Wo2[cta * 4 + tid];
    }
    const float bo2 = bo2p[0];

    // gi0 ctx part (time-invariant): base[g*64+b] = Wih0[grow,:512].ctx[b]+bih0
    {
        int warp = tid >> 5, lane = tid & 31;
        for (int d = warp; d < 12 * 64; d += 16) {
            int g = d >> 6, b = d & 63;
            int grow = (g >> 2) * 512 + cta * 4 + (g & 3);
            const float* wr = Wih0 + (size_t)grow * 513;
            const float* cx = ctx + b * 512;
            float a = 0.0f;
            #pragma unroll 4
            for (int k = lane; k < 512; k += 32) a = fmaf(wr[k], cx[k], a);
            #pragma unroll
            for (int o = 16; o > 0; o >>= 1) a += __shfl_down_sync(0xffffffffu, a, o);
            if (lane == 0) base[g * 64 + b] = a + bih0[grow];
        }
    }

    // zero redBh (t=0: Bh of h1=0) and initial global state
    for (int idx = tid; idx < 12288; idx += NTHR) redBh[idx] = 0.0f;
    {
        int i = cta * NTHR + tid;
        if (i < HB) { g_h0[0][i] = 0.0f; g_h1[0][i] = 0.0f; }
        if (cta == 0 && tid < BATCH) { g_yacc[0][tid] = 0.0f; g_yacc[1][tid] = 0.0f; }
    }

    unsigned bg = ldacq(&g_gen);   // persistent across graph replays: relative
    bar_arrive(++bg);
    bar_wait(bg);

    // Loop-invariant gi0 sums + carried GEMV sums (valid for tid<256).
    float ir0 = 0, iz0 = 0, in0 = 0;          // base (constant over t)
    float c_hr = 0, c_hz = 0, c_hn = 0;       // bhh0 + Whh0.h0(t)
    float wcR = 0, wcZ = 0, wcN = 0;
    if (tid < 256) {
        ir0 = base[gR * 64 + be]; iz0 = base[gZ * 64 + be]; in0 = base[gN * 64 + be];
        c_hr = bhhA[gR]; c_hz = bhhA[gZ]; c_hn = bhhA[gN];
        wcR = wcolA[gR]; wcZ = wcolA[gZ]; wcN = wcolA[gN];
    }
    float c_br = 0, c_bz = 0, c_bn = 0;       // bhh1 + Whh1.h1(t), set per step

    // ---- main recurrence ---------------------------------------------------
    for (int t = 0; t < TSTEPS; t++) {
        const int p = t & 1;

        // ===== phase 1: h0n from carried sums + y(t-1) ======================
        if (tid < 256) {
            float prev_y = 0.0f;
            if (t > 0) prev_y = fmaxf(__ldcg(&g_yacc[(t - 1) & 1][be]) + bo2, 0.0f);
            float r = sigm(ir0 + prev_y * wcR + c_hr);
            float z = sigm(iz0 + prev_y * wcZ + c_hz);
            float n = tanh_f(in0 + prev_y * wcN + r * c_hn);
            float hold = __ldcg(&g_h0[p][jrow * 64 + be]);
            g_h0[1 - p][jrow * 64 + be] = (1.0f - z) * n + z * hold;
            if (cta == 0 && t > 0 && re == 0) out[be * TSTEPS + (t - 1)] = prev_y;
        }
        bar_arrive(++bg);                        // alpha: h0n published

        // Bh(t) reduction under alpha (partials from pass-Y of step t-1)
        if (tid < 256) {
            float sr = bhB[gR], sz = bhB[gZ], sn = bhB[gN];
            #pragma unroll
            for (int sl = 0; sl < 16; sl++) {
                sr += redBh[(gR * 16 + sl) * 64 + be];
                sz += redBh[(gZ * 16 + sl) * 64 + be];
                sn += redBh[(gN * 16 + sl) * 64 + be];
            }
            c_br = sr; c_bz = sz; c_bn = sn;
        }
        bar_wait(bg);                            // alpha
        if (cta == 1 && tid < BATCH) __stcg(&g_yacc[(t + 1) & 1][tid], 0.0f);

        // ===== pass-X on h0n: Bi(t) + A(t+1) ================================
        const float* xp = g_h0[1 - p];
        {
            u64 aBi[12], aA[12];
            #pragma unroll
            for (int g = 0; g < 12; g++) { aBi[g] = 0ull; aA[g] = 0ull; }
            #pragma unroll
            for (int blk = 0; blk < 4; blk++) {
                const int k0 = kb + blk * 8;
                float2 v[8];
                #pragma unroll
                for (int i = 0; i < 8; i++)
                    v[i] = __ldcg((const float2*)(xp + (k0 + i) * 64 + b0));
                #pragma unroll
                for (int i = 0; i < 8; i++) {
                    u64 va = dup(v[i].x), vb = dup(v[i].y);
                    const ulonglong2* wi = (const ulonglong2*)(wBi + (k0 + i) * 12);
                    ulonglong2 w01 = wi[0], w23 = wi[1], w45 = wi[2];
                    fma2(aBi[0],  w01.x, va); fma2(aBi[1],  w01.x, vb);
                    fma2(aBi[2],  w01.y, va); fma2(aBi[3],  w01.y, vb);
                    fma2(aBi[4],  w23.x, va); fma2(aBi[5],  w23.x, vb);
                    fma2(aBi[6],  w23.y, va); fma2(aBi[7],  w23.y, vb);
                    fma2(aBi[8],  w45.x, va); fma2(aBi[9],  w45.x, vb);
                    fma2(aBi[10], w45.y, va); fma2(aBi[11], w45.y, vb);
                    const ulonglong2* wa = (const ulonglong2*)(wA + (k0 + i) * 12);
                    ulonglong2 a01 = wa[0], a23 = wa[1], a45 = wa[2];
                    fma2(aA[0],  a01.x, va); fma2(aA[1],  a01.x, vb);
                    fma2(aA[2],  a01.y, va); fma2(aA[3],  a01.y, vb);
                    fma2(aA[4],  a23.x, va); fma2(aA[5],  a23.x, vb);
                    fma2(aA[6],  a23.y, va); fma2(aA[7],  a23.y, vb);
                    fma2(aA[8],  a45.x, va); fma2(aA[9],  a45.x, vb);
                    fma2(aA[10], a45.y, va); fma2(aA[11], a45.y, vb);
                }
            }
            store12(redBi, aBi, ks, b0);
            store12(redA,  aA,  ks, b0);
        }
        __syncthreads();
        if (tid < 256) {
            float ir = biB[gR], iz = biB[gZ], in_ = biB[gN];
            #pragma unroll
            for (int sl = 0; sl < 16; sl++) {
                ir  += redBi[(gR * 16 + sl) * 64 + be];
                iz  += redBi[(gZ * 16 + sl) * 64 + be];
                in_ += redBi[(gN * 16 + sl) * 64 + be];
            }
            float r = sigm(ir + c_br);
            float z = sigm(iz + c_bz);
            float n = tanh_f(in_ + r * c_bn);
            float hold = __ldcg(&g_h1[p][jrow * 64 + be]);
            g_h1[1 - p][jrow * 64 + be] = (1.0f - z) * n + z * hold;
        }
        bar_arrive(++bg);                        // beta: h1n published

        // A(t+1) reduction under beta
        if (tid < 256) {
            float hr = bhhA[gR], hz = bhhA[gZ], hn = bhhA[gN];
            #pragma unroll
            for (int sl = 0; sl < 16; sl++) {
                hr += redA[(gR * 16 + sl) * 64 + be];
                hz += redA[(gZ * 16 + sl) * 64 + be];
                hn += redA[(gN * 16 + sl) * 64 + be];
            }
            c_hr = hr; c_hz = hz; c_hn = hn;
        }
        bar_wait(bg);                            // beta

        // ===== pass-Y on h1n: C(t) + Bh(t+1) ================================
        const float* yp = g_h1[1 - p];
        {
            u64 aC[4], aBh[12];
            #pragma unroll
            for (int r = 0; r < 4; r++) aC[r] = 0ull;
            #pragma unroll
            for (int g = 0; g < 12; g++) aBh[g] = 0ull;
            #pragma unroll
            for (int blk = 0; blk < 4; blk++) {
                const int k0 = kb + blk * 8;
                float2 v[8];
                #pragma unroll
                for (int i = 0; i < 8; i++)
                    v[i] = __ldcg((const float2*)(yp + (k0 + i) * 64 + b0));
                #pragma unroll
                for (int i = 0; i < 8; i++) {
                    u64 va = dup(v[i].x), vb = dup(v[i].y);
                    ulonglong2 wc = *(const ulonglong2*)(wC + (k0 + i) * 4);
                    fma2(aC[0], wc.x, va); fma2(aC[1], wc.x, vb);
                    fma2(aC[2], wc.y, va); fma2(aC[3], wc.y, vb);
                    const ulonglong2* wh = (const ulonglong2*)(wBh + (k0 + i) * 12);
                    ulonglong2 w01 = wh[0], w23 = wh[1], w45 = wh[2];
                    fma2(aBh[0],  w01.x, va); fma2(aBh[1],  w01.x, vb);
                    fma2(aBh[2],  w01.y, va); fma2(aBh[3],  w01.y, vb);
                    fma2(aBh[4],  w23.x, va); fma2(aBh[5],  w23.x, vb);
                    fma2(aBh[6],  w23.y, va); fma2(aBh[7],  w23.y, vb);
                    fma2(aBh[8],  w45.x, va); fma2(aBh[9],  w45.x, vb);
                    fma2(aBh[10], w45.y, va); fma2(aBh[11], w45.y, vb);
                }
            }
            #pragma unroll
            for (int pr = 0; pr < 2; pr++) {
                #pragma unroll
                for (int j = 0; j < 2; j++) {
                    float2 f = unpack2(aC[2 * pr + j]);
                    redC[((2 * pr)     * 16 + ks) * 64 + b0 + j] = f.x;
                    redC[((2 * pr + 1) * 16 + ks) * 64 + b0 + j] = f.y;
                }
            }
            store12(redBh, aBh, ks, b0);
        }
        __syncthreads();
        if (tid < 256) {
            float s = bC[re];
            #pragma unroll
            for (int sl = 0; sl < 16; sl++) s += redC[(re * 16 + sl) * 64 + be];
            y2[re * 64 + be] = fmaxf(s, 0.0f) * wo2s[re];
        }
        __syncthreads();
        if (tid < 64) {
            float v = y2[tid] + y2[64 + tid] + y2[128 + tid] + y2[192 + tid];
            atomicAdd(&g_yacc[t & 1][tid], v);
        }
        bar_arrive(++bg);                        // gamma: y published
        bar_wait(bg);                            // gamma (exposed)
    }

    // ---- epilogue ----------------------------------------------------------
    if (cta == 0 && tid < BATCH)
        out[tid * TSTEPS + (TSTEPS - 1)] = fmaxf(__ldcg(&g_yacc[1][tid]) + bo2, 0.0f);
    if (out_size >= BT + 2 * BH && tid < 256) {
        // final hidden states live in buffer 0 (t=1023: 1-p = 0)
        out[BT + be * HID + jrow]      = __ldcg(&g_h0[0][jrow * 64 + be]);
        out[BT + BH + be * HID + jrow] = __ldcg(&g_h1[0][jrow * 64 + be]);
    }
}

extern "C" void kernel_launch(void* const* d_in, const int* in_sizes, int n_in,
                              void* d_out, int out_size) {
    (void)in_sizes; (void)n_in;
    cudaFuncSetAttribute(decoder_rnn, cudaFuncAttributeMaxDynamicSharedMemorySize,
                         SMEM_BYTES);
    decoder_rnn<<<NCTA, NTHR, SMEM_BYTES>>>(
        (const float*)d_in[0],                           // context_vector
        (const float*)d_in[2],  (const float*)d_in[3],   // W_ih0, W_hh0
        (const float*)d_in[4],  (const float*)d_in[5],   // b_ih0, b_hh0
        (const float*)d_in[6],  (const float*)d_in[7],   // W_ih1, W_hh1
        (const float*)d_in[8],  (const float*)d_in[9],   // b_ih1, b_hh1
        (const float*)d_in[10], (const float*)d_in[11],  // W_o1, b_o1
        (const float*)d_in[12], (const float*)d_in[13],  // W_o2, b_o2
        (float*)d_out, out_size);
}